// round 1
// baseline (speedup 1.0000x reference)
#include <cuda_runtime.h>

#define BS      512
#define DIM     128
#define POS_K   32
#define NUM_NEG 1024
#define INV_TEMP (1.0f / 0.07f)

// Output layout (flattened tuple, float32):
// o0 inst_v2a_pos [512,1]      @ 0
// o1 inst_v2a_neg [512,1024]   @ 512
// o2 inst_a2v_pos [512,1]      @ 524800
// o3 inst_a2v_neg [512,1024]   @ 525312
// o4 pos_v2v_pos  [512,32]     @ 1049600
// o5 pos_v2v_neg  [512,1024]   @ 1065984
// o6 pos_a2a_pos  [512,32]     @ 1590272
// o7 pos_a2a_neg  [512,1024]   @ 1606656
#define O0 0
#define O1 512
#define O2 524800
#define O3 525312
#define O4 1049600
#define O5 1065984
#define O6 1590272
#define O7 1606656

__device__ __forceinline__ float warp_sum(float x) {
#pragma unroll
    for (int o = 16; o; o >>= 1) x += __shfl_xor_sync(0xffffffffu, x, o);
    return x;
}

__device__ __forceinline__ void warp_sum4(float& a, float& b, float& c, float& d) {
#pragma unroll
    for (int o = 16; o; o >>= 1) {
        a += __shfl_xor_sync(0xffffffffu, a, o);
        b += __shfl_xor_sync(0xffffffffu, b, o);
        c += __shfl_xor_sync(0xffffffffu, c, o);
        d += __shfl_xor_sync(0xffffffffu, d, o);
    }
}

__device__ __forceinline__ float dot4(float4 x, float4 y) {
    return x.x * y.x + x.y * y.y + x.z * y.z + x.w * y.w;
}

__global__ __launch_bounds__(512, 2)
void avid_cma_kernel(const float* __restrict__ video,
                     const float* __restrict__ audio,
                     const float4* __restrict__ m1,   // view1_mem as rows of 32 float4
                     const float4* __restrict__ m2,   // view2_mem
                     const int* __restrict__ y,
                     const int* __restrict__ pos_idx,
                     const int* __restrict__ neg_idx,
                     float* __restrict__ out)
{
    const int b    = blockIdx.x;
    const int tid  = threadIdx.x;
    const int lane = tid & 31;
    const int w    = tid >> 5;          // 16 warps

    __shared__ float sv[DIM];
    __shared__ float sa[DIM];

    // --- normalize fresh embeddings (warp 0: video, warp 1: audio) ---
    if (w == 0) {
        float4 x = reinterpret_cast<const float4*>(video + (size_t)b * DIM)[lane];
        float ss = warp_sum(dot4(x, x));
        float inv = 1.0f / fmaxf(sqrtf(ss), 1e-12f);
        reinterpret_cast<float4*>(sv)[lane] =
            make_float4(x.x * inv, x.y * inv, x.z * inv, x.w * inv);
    } else if (w == 1) {
        float4 x = reinterpret_cast<const float4*>(audio + (size_t)b * DIM)[lane];
        float ss = warp_sum(dot4(x, x));
        float inv = 1.0f / fmaxf(sqrtf(ss), 1e-12f);
        reinterpret_cast<float4*>(sa)[lane] =
            make_float4(x.x * inv, x.y * inv, x.z * inv, x.w * inv);
    }
    __syncthreads();

    const float4 v4 = reinterpret_cast<const float4*>(sv)[lane];
    const float4 a4 = reinterpret_cast<const float4*>(sa)[lane];

    // --- self dots (warp 0) ---
    if (w == 0) {
        const int yi = __ldg(y + b);
        float4 r1 = m1[(size_t)yi * 32 + lane];
        float4 r2 = m2[(size_t)yi * 32 + lane];
        float da1 = dot4(r1, a4);   // view1[y]·a -> inst_a2v_pos
        float dv2 = dot4(r2, v4);   // view2[y]·v -> inst_v2a_pos
        float dummy0 = 0.f, dummy1 = 0.f;
        warp_sum4(da1, dv2, dummy0, dummy1);
        if (lane == 0) {
            out[O0 + b] = dv2 * INV_TEMP;
            out[O2 + b] = da1 * INV_TEMP;
        }
    }

    // --- positive dots: 32 per row, 2 dots each ---
    const int* pb = pos_idx + (size_t)b * POS_K;
    for (int j = w; j < POS_K; j += 16) {
        const int pi = __ldg(pb + j);
        float4 r1 = m1[(size_t)pi * 32 + lane];
        float4 r2 = m2[(size_t)pi * 32 + lane];
        float dvv = dot4(r1, v4);   // view1[pos]·v -> pos_v2v_pos
        float daa = dot4(r2, a4);   // view2[pos]·a -> pos_a2a_pos
        float dummy0 = 0.f, dummy1 = 0.f;
        warp_sum4(dvv, daa, dummy0, dummy1);
        if (lane == 0) {
            out[O4 + (size_t)b * POS_K + j] = dvv * INV_TEMP;
            out[O6 + (size_t)b * POS_K + j] = daa * INV_TEMP;
        }
    }

    // --- negative dots: 1024 per row, 4 dots each (the 512 MB gather) ---
    const int* nb = neg_idx + (size_t)b * NUM_NEG;
#pragma unroll 2
    for (int j = w; j < NUM_NEG; j += 16) {
        const int ni = __ldg(nb + j);
        const float4 r1 = m1[(size_t)ni * 32 + lane];
        const float4 r2 = m2[(size_t)ni * 32 + lane];
        float dv1 = dot4(r1, v4);   // view1·v -> pos_v2v_neg
        float da1 = dot4(r1, a4);   // view1·a -> inst_a2v_neg
        float dv2 = dot4(r2, v4);   // view2·v -> inst_v2a_neg
        float da2 = dot4(r2, a4);   // view2·a -> pos_a2a_neg
        warp_sum4(dv1, da1, dv2, da2);
        if (lane == 0) {
            const size_t o = (size_t)b * NUM_NEG + j;
            out[O1 + o] = dv2 * INV_TEMP;
            out[O3 + o] = da1 * INV_TEMP;
            out[O5 + o] = dv1 * INV_TEMP;
            out[O7 + o] = da2 * INV_TEMP;
        }
    }
}

extern "C" void kernel_launch(void* const* d_in, const int* in_sizes, int n_in,
                              void* d_out, int out_size)
{
    const float* video = (const float*)d_in[0];
    const float* audio = (const float*)d_in[1];
    const float4* m1   = (const float4*)d_in[2];
    const float4* m2   = (const float4*)d_in[3];
    const int* y       = (const int*)d_in[4];
    const int* pos_idx = (const int*)d_in[5];
    const int* neg_idx = (const int*)d_in[6];
    float* out         = (float*)d_out;

    avid_cma_kernel<<<BS, 512>>>(video, audio, m1, m2, y, pos_idx, neg_idx, out);
}

// round 2
// speedup vs baseline: 1.0590x; 1.0590x over previous
#include <cuda_runtime.h>

#define BS      512
#define DIM     128
#define POS_K   32
#define NUM_NEG 1024
#define NEG_PER_BLK 256
#define INV_TEMP (1.0f / 0.07f)

// Output layout (flattened tuple, float32):
#define O0 0          // inst_v2a_pos [512,1]
#define O1 512        // inst_v2a_neg [512,1024]
#define O2 524800     // inst_a2v_pos [512,1]
#define O3 525312     // inst_a2v_neg [512,1024]
#define O4 1049600    // pos_v2v_pos  [512,32]
#define O5 1065984    // pos_v2v_neg  [512,1024]
#define O6 1590272    // pos_a2a_pos  [512,32]
#define O7 1606656    // pos_a2a_neg  [512,1024]

__device__ __forceinline__ float warp_sum(float x) {
#pragma unroll
    for (int o = 16; o; o >>= 1) x += __shfl_xor_sync(0xffffffffu, x, o);
    return x;
}

__device__ __forceinline__ float dot4(float4 x, float4 y) {
    return x.x * y.x + x.y * y.y + x.z * y.z + x.w * y.w;
}

// reduce over groups of 8 lanes (xor of low 3 lane bits)
__device__ __forceinline__ void grp8_sum4(float& a, float& b, float& c, float& d) {
#pragma unroll
    for (int o = 4; o; o >>= 1) {
        a += __shfl_xor_sync(0xffffffffu, a, o);
        b += __shfl_xor_sync(0xffffffffu, b, o);
        c += __shfl_xor_sync(0xffffffffu, c, o);
        d += __shfl_xor_sync(0xffffffffu, d, o);
    }
}

__device__ __forceinline__ void grp8_sum2(float& a, float& b) {
#pragma unroll
    for (int o = 4; o; o >>= 1) {
        a += __shfl_xor_sync(0xffffffffu, a, o);
        b += __shfl_xor_sync(0xffffffffu, b, o);
    }
}

__global__ __launch_bounds__(256)
void avid_cma_kernel(const float* __restrict__ video,
                     const float* __restrict__ audio,
                     const float4* __restrict__ m1,
                     const float4* __restrict__ m2,
                     const int* __restrict__ y,
                     const int* __restrict__ pos_idx,
                     const int* __restrict__ neg_idx,
                     float* __restrict__ out)
{
    const int b    = blockIdx.x;
    const int q    = blockIdx.y;        // negative chunk [q*256, q*256+256)
    const int tid  = threadIdx.x;
    const int lane = tid & 31;
    const int w    = tid >> 5;          // 8 warps
    const int c    = lane & 7;          // float4-chunk within row (covers c, c+8, c+16, c+24)
    const int r    = lane >> 3;         // row within warp's group of 4

    __shared__ float4 sv[32];
    __shared__ float4 sa[32];

    // --- normalize fresh embeddings (warp 0: video, warp 1: audio) ---
    if (w == 0) {
        float4 x = reinterpret_cast<const float4*>(video)[b * 32 + lane];
        float ss = warp_sum(dot4(x, x));
        float inv = 1.0f / fmaxf(sqrtf(ss), 1e-12f);
        sv[lane] = make_float4(x.x * inv, x.y * inv, x.z * inv, x.w * inv);
    } else if (w == 1) {
        float4 x = reinterpret_cast<const float4*>(audio)[b * 32 + lane];
        float ss = warp_sum(dot4(x, x));
        float inv = 1.0f / fmaxf(sqrtf(ss), 1e-12f);
        sa[lane] = make_float4(x.x * inv, x.y * inv, x.z * inv, x.w * inv);
    }
    __syncthreads();

    // this lane's 16-float slice of v and a (positions c, c+8, c+16, c+24)
    const float4 v0 = sv[c], v1 = sv[c + 8], v2 = sv[c + 16], v3 = sv[c + 24];
    const float4 a0 = sa[c], a1 = sa[c + 8], a2 = sa[c + 16], a3 = sa[c + 24];

    // --- pos + self dots (only in the q==0 slice) ---
    if (q == 0) {
        // positives: warp w handles pos j = w*4 + r  (8 warps * 4 = all 32)
        const int j  = w * 4 + r;
        const int pi = __ldg(pos_idx + (size_t)b * POS_K + j);
        const float4* p1 = m1 + (size_t)pi * 32 + c;
        const float4* p2 = m2 + (size_t)pi * 32 + c;
        float dvv = dot4(p1[0], v0) + dot4(p1[8], v1) + dot4(p1[16], v2) + dot4(p1[24], v3);
        float daa = dot4(p2[0], a0) + dot4(p2[8], a1) + dot4(p2[16], a2) + dot4(p2[24], a3);
        grp8_sum2(dvv, daa);
        if (c == 0) {
            out[O4 + (size_t)b * POS_K + j] = dvv * INV_TEMP;
            out[O6 + (size_t)b * POS_K + j] = daa * INV_TEMP;
        }

        // self dots: warp 0, groups r=0 (m1[y]·a) and r=1 (m2[y]·v)
        if (w == 0 && r < 2) {
            const int yi = __ldg(y + b);
            const float4* p = (r == 0 ? m1 : m2) + (size_t)yi * 32 + c;
            float d;
            if (r == 0) d = dot4(p[0], a0) + dot4(p[8], a1) + dot4(p[16], a2) + dot4(p[24], a3);
            else        d = dot4(p[0], v0) + dot4(p[8], v1) + dot4(p[16], v2) + dot4(p[24], v3);
#pragma unroll
            for (int o = 4; o; o >>= 1) d += __shfl_xor_sync(0x0000ffffu, d, o);
            if (c == 0) {
                if (r == 0) out[O2 + b] = d * INV_TEMP;  // inst_a2v_pos
                else        out[O0 + b] = d * INV_TEMP;  // inst_v2a_pos
            }
        }
    }

    // --- negatives: 256 per block, 4 per warp-iteration, 8 iterations ---
    const int* nb = neg_idx + (size_t)b * NUM_NEG + (size_t)q * NEG_PER_BLK;
    for (int it = 0; it < 8; ++it) {
        const int j  = (it * 8 + w) * 4 + r;       // 0..255
        const int ni = __ldg(nb + j);
        const float4* p1 = m1 + (size_t)ni * 32 + c;
        const float4* p2 = m2 + (size_t)ni * 32 + c;
        // 8 independent 16B loads in flight
        const float4 x10 = p1[0], x11 = p1[8], x12 = p1[16], x13 = p1[24];
        const float4 x20 = p2[0], x21 = p2[8], x22 = p2[16], x23 = p2[24];

        float dv1 = dot4(x10, v0) + dot4(x11, v1) + dot4(x12, v2) + dot4(x13, v3);
        float da1 = dot4(x10, a0) + dot4(x11, a1) + dot4(x12, a2) + dot4(x13, a3);
        float dv2 = dot4(x20, v0) + dot4(x21, v1) + dot4(x22, v2) + dot4(x23, v3);
        float da2 = dot4(x20, a0) + dot4(x21, a1) + dot4(x22, a2) + dot4(x23, a3);
        grp8_sum4(dv1, da1, dv2, da2);

        if (c == 0) {
            const size_t o = (size_t)b * NUM_NEG + (size_t)q * NEG_PER_BLK + j;
            out[O1 + o] = dv2 * INV_TEMP;  // inst_v2a_neg = a_neg·v
            out[O3 + o] = da1 * INV_TEMP;  // inst_a2v_neg = v_neg·a
            out[O5 + o] = dv1 * INV_TEMP;  // pos_v2v_neg  = v_neg·v
            out[O7 + o] = da2 * INV_TEMP;  // pos_a2a_neg  = a_neg·a
        }
    }
}

extern "C" void kernel_launch(void* const* d_in, const int* in_sizes, int n_in,
                              void* d_out, int out_size)
{
    const float* video = (const float*)d_in[0];
    const float* audio = (const float*)d_in[1];
    const float4* m1   = (const float4*)d_in[2];
    const float4* m2   = (const float4*)d_in[3];
    const int* y       = (const int*)d_in[4];
    const int* pos_idx = (const int*)d_in[5];
    const int* neg_idx = (const int*)d_in[6];
    float* out         = (float*)d_out;

    dim3 grid(BS, NUM_NEG / NEG_PER_BLK);  // 512 x 4
    avid_cma_kernel<<<grid, 256>>>(video, audio, m1, m2, y, pos_idx, neg_idx, out);
}

// round 3
// speedup vs baseline: 1.2621x; 1.1919x over previous
#include <cuda_runtime.h>
#include <cstdint>

#define BS      512
#define DIM     128
#define POS_K   32
#define NUM_NEG 1024
#define NEG_PER_BLK 256
#define INV_TEMP (1.0f / 0.07f)

#define D_ST    6                         // pipeline depth (stages in flight)
#define NEG_ST  16                        // negatives per stage
#define ROWS_ST (NEG_ST * 2)              // 32 rows (m1+m2) per stage
#define STAGE_B (ROWS_ST * 512)           // 16 KB per stage
#define N_STAGE (NEG_PER_BLK / NEG_ST)    // 16 stages per block

// Output layout (flattened tuple, float32):
#define O0 0          // inst_v2a_pos [512,1]
#define O1 512        // inst_v2a_neg [512,1024]
#define O2 524800     // inst_a2v_pos [512,1]
#define O3 525312     // inst_a2v_neg [512,1024]
#define O4 1049600    // pos_v2v_pos  [512,32]
#define O5 1065984    // pos_v2v_neg  [512,1024]
#define O6 1590272    // pos_a2a_pos  [512,32]
#define O7 1606656    // pos_a2a_neg  [512,1024]

__device__ __forceinline__ float warp_sum(float x) {
#pragma unroll
    for (int o = 16; o; o >>= 1) x += __shfl_xor_sync(0xffffffffu, x, o);
    return x;
}

__device__ __forceinline__ float dot4(float4 x, float4 y) {
    return x.x * y.x + x.y * y.y + x.z * y.z + x.w * y.w;
}

__device__ __forceinline__ void grp8_sum2(float& a, float& b) {
#pragma unroll
    for (int o = 4; o; o >>= 1) {
        a += __shfl_xor_sync(0xffffffffu, a, o);
        b += __shfl_xor_sync(0xffffffffu, b, o);
    }
}

__device__ __forceinline__ void cp_async16(uint32_t dst_smem, const void* src) {
    asm volatile("cp.async.cg.shared.global [%0], [%1], 16;\n"
                 :: "r"(dst_smem), "l"(src) : "memory");
}
__device__ __forceinline__ void cp_commit() {
    asm volatile("cp.async.commit_group;\n" ::: "memory");
}
template <int N>
__device__ __forceinline__ void cp_wait() {
    asm volatile("cp.async.wait_group %0;\n" :: "n"(N) : "memory");
}

__global__ __launch_bounds__(256)
void avid_cma_kernel(const float* __restrict__ video,
                     const float* __restrict__ audio,
                     const float4* __restrict__ m1,
                     const float4* __restrict__ m2,
                     const int* __restrict__ y,
                     const int* __restrict__ pos_idx,
                     const int* __restrict__ neg_idx,
                     float* __restrict__ out)
{
    extern __shared__ char ring[];            // D_ST * STAGE_B
    __shared__ int    sidx[NEG_PER_BLK];
    __shared__ float4 sv[32];
    __shared__ float4 sa[32];
    __shared__ float  sout[4][NEG_PER_BLK];   // O1,O3,O5,O7 staging

    const int b    = blockIdx.x;
    const int q    = blockIdx.y;
    const int tid  = threadIdx.x;
    const int lane = tid & 31;
    const int w    = tid >> 5;          // 8 warps
    const int c    = lane & 7;          // chunk within row (c, c+8, c+16, c+24)
    const int r    = lane >> 3;         // 8-lane group id in warp

    // --- preload this block's 256 negative indices ---
    sidx[tid] = __ldg(neg_idx + (size_t)b * NUM_NEG + (size_t)q * NEG_PER_BLK + tid);

    // --- normalize fresh embeddings ---
    if (w == 0) {
        float4 x = reinterpret_cast<const float4*>(video)[b * 32 + lane];
        float ss = warp_sum(dot4(x, x));
        float inv = 1.0f / fmaxf(sqrtf(ss), 1e-12f);
        sv[lane] = make_float4(x.x * inv, x.y * inv, x.z * inv, x.w * inv);
    } else if (w == 1) {
        float4 x = reinterpret_cast<const float4*>(audio)[b * 32 + lane];
        float ss = warp_sum(dot4(x, x));
        float inv = 1.0f / fmaxf(sqrtf(ss), 1e-12f);
        sa[lane] = make_float4(x.x * inv, x.y * inv, x.z * inv, x.w * inv);
    }
    __syncthreads();

    const float4 v0 = sv[c], v1 = sv[c + 8], v2 = sv[c + 16], v3 = sv[c + 24];
    const float4 a0 = sa[c], a1 = sa[c + 8], a2 = sa[c + 16], a3 = sa[c + 24];

    // --- prologue: issue first D_ST-1 stages ---
#pragma unroll
    for (int s = 0; s < D_ST - 1; ++s) {
#pragma unroll
        for (int i = 0; i < 4; ++i) {
            const int t    = w * 4 + i;                 // row slot 0..31
            const int ni   = sidx[s * NEG_ST + (t >> 1)];
            const float4* src = ((t & 1) ? m2 : m1) + (size_t)ni * 32 + lane;
            uint32_t dst = (uint32_t)__cvta_generic_to_shared(
                ring + (size_t)s * STAGE_B + (size_t)t * 512 + lane * 16);
            cp_async16(dst, src);
        }
        cp_commit();
    }

    // --- pos + self dots (q==0 only), plain LDG while pipeline fills ---
    if (q == 0) {
        const int j  = w * 4 + r;
        const int pi = __ldg(pos_idx + (size_t)b * POS_K + j);
        const float4* p1 = m1 + (size_t)pi * 32 + c;
        const float4* p2 = m2 + (size_t)pi * 32 + c;
        float dvv = dot4(p1[0], v0) + dot4(p1[8], v1) + dot4(p1[16], v2) + dot4(p1[24], v3);
        float daa = dot4(p2[0], a0) + dot4(p2[8], a1) + dot4(p2[16], a2) + dot4(p2[24], a3);
        grp8_sum2(dvv, daa);
        if (c == 0) {
            out[O4 + (size_t)b * POS_K + j] = dvv * INV_TEMP;
            out[O6 + (size_t)b * POS_K + j] = daa * INV_TEMP;
        }
        if (w == 0 && r < 2) {
            const int yi = __ldg(y + b);
            const float4* p = (r == 0 ? m1 : m2) + (size_t)yi * 32 + c;
            float d;
            if (r == 0) d = dot4(p[0], a0) + dot4(p[8], a1) + dot4(p[16], a2) + dot4(p[24], a3);
            else        d = dot4(p[0], v0) + dot4(p[8], v1) + dot4(p[16], v2) + dot4(p[24], v3);
#pragma unroll
            for (int o = 4; o; o >>= 1) d += __shfl_xor_sync(0x0000ffffu, d, o);
            if (c == 0) {
                if (r == 0) out[O2 + b] = d * INV_TEMP;  // inst_a2v_pos
                else        out[O0 + b] = d * INV_TEMP;  // inst_v2a_pos
            }
        }
    }

    // --- main pipeline: 16 stages of 16 negatives ---
    const int t = w * 4 + r;                    // this group's row slot (fixed)
    for (int s = 0; s < N_STAGE; ++s) {
        cp_wait<D_ST - 2>();                    // stage s data landed (own groups)
        __syncthreads();                        // make it visible across warps

        // compute: group handles row slot t of stage s
        {
            const float4* buf = reinterpret_cast<const float4*>(
                ring + (size_t)(s % D_ST) * STAGE_B) + (size_t)t * 32;
            const float4 x0 = buf[c], x1 = buf[c + 8], x2 = buf[c + 16], x3 = buf[c + 24];
            float dv = dot4(x0, v0) + dot4(x1, v1) + dot4(x2, v2) + dot4(x3, v3);
            float da = dot4(x0, a0) + dot4(x1, a1) + dot4(x2, a2) + dot4(x3, a3);
            grp8_sum2(dv, da);
            if (c == 0) {
                const int j = s * NEG_ST + (t >> 1);
                if ((t & 1) == 0) {             // m1 row: ·a -> O3, ·v -> O5
                    sout[1][j] = da * INV_TEMP;
                    sout[2][j] = dv * INV_TEMP;
                } else {                        // m2 row: ·v -> O1, ·a -> O7
                    sout[0][j] = dv * INV_TEMP;
                    sout[3][j] = da * INV_TEMP;
                }
            }
        }

        // issue stage s + D_ST - 1 (slot (s-1)%D_ST, whose compute finished last iter)
        const int sn = s + D_ST - 1;
        if (sn < N_STAGE) {
#pragma unroll
            for (int i = 0; i < 4; ++i) {
                const int tt = w * 4 + i;
                const int ni = sidx[sn * NEG_ST + (tt >> 1)];
                const float4* src = ((tt & 1) ? m2 : m1) + (size_t)ni * 32 + lane;
                uint32_t dst = (uint32_t)__cvta_generic_to_shared(
                    ring + (size_t)(sn % D_ST) * STAGE_B + (size_t)tt * 512 + lane * 16);
                cp_async16(dst, src);
            }
        }
        cp_commit();                            // always commit (empty groups keep count)
    }

    // --- coalesced output flush ---
    __syncthreads();
    const size_t o = (size_t)b * NUM_NEG + (size_t)q * NEG_PER_BLK + tid;
    out[O1 + o] = sout[0][tid];
    out[O3 + o] = sout[1][tid];
    out[O5 + o] = sout[2][tid];
    out[O7 + o] = sout[3][tid];
}

extern "C" void kernel_launch(void* const* d_in, const int* in_sizes, int n_in,
                              void* d_out, int out_size)
{
    const float* video = (const float*)d_in[0];
    const float* audio = (const float*)d_in[1];
    const float4* m1   = (const float4*)d_in[2];
    const float4* m2   = (const float4*)d_in[3];
    const int* y       = (const int*)d_in[4];
    const int* pos_idx = (const int*)d_in[5];
    const int* neg_idx = (const int*)d_in[6];
    float* out         = (float*)d_out;

    const int dyn_smem = D_ST * STAGE_B;   // 96 KB
    cudaFuncSetAttribute(avid_cma_kernel,
                         cudaFuncAttributeMaxDynamicSharedMemorySize, dyn_smem);

    dim3 grid(BS, NUM_NEG / NEG_PER_BLK);  // 512 x 4
    avid_cma_kernel<<<grid, 256, dyn_smem>>>(video, audio, m1, m2, y,
                                             pos_idx, neg_idx, out);
}

// round 4
// speedup vs baseline: 1.3842x; 1.0967x over previous
#include <cuda_runtime.h>
#include <cstdint>

#define BS      512
#define DIM     128
#define POS_K   32
#define NUM_NEG 1024
#define NEG_PER_BLK 256
#define INV_TEMP (1.0f / 0.07f)

#define D_ST    6                         // pipeline depth (stages in flight)
#define NEG_ST  16                        // negatives per stage
#define ROWS_ST (NEG_ST * 2)              // 32 rows (m1+m2) per stage
#define STAGE_B (ROWS_ST * 512)           // 16 KB per stage
#define N_STAGE (NEG_PER_BLK / NEG_ST)    // 16 stages per block

// Output layout (flattened tuple, float32):
#define O0 0          // inst_v2a_pos [512,1]
#define O1 512        // inst_v2a_neg [512,1024]
#define O2 524800     // inst_a2v_pos [512,1]
#define O3 525312     // inst_a2v_neg [512,1024]
#define O4 1049600    // pos_v2v_pos  [512,32]
#define O5 1065984    // pos_v2v_neg  [512,1024]
#define O6 1590272    // pos_a2a_pos  [512,32]
#define O7 1606656    // pos_a2a_neg  [512,1024]

__device__ __forceinline__ float warp_sum(float x) {
#pragma unroll
    for (int o = 16; o; o >>= 1) x += __shfl_xor_sync(0xffffffffu, x, o);
    return x;
}

__device__ __forceinline__ float dot4(float4 x, float4 y) {
    return x.x * y.x + x.y * y.y + x.z * y.z + x.w * y.w;
}

__device__ __forceinline__ void grp8_sum2(float& a, float& b) {
#pragma unroll
    for (int o = 4; o; o >>= 1) {
        a += __shfl_xor_sync(0xffffffffu, a, o);
        b += __shfl_xor_sync(0xffffffffu, b, o);
    }
}

__device__ __forceinline__ void cp_async16(uint32_t dst_smem, const void* src) {
    asm volatile("cp.async.cg.shared.global [%0], [%1], 16;\n"
                 :: "r"(dst_smem), "l"(src) : "memory");
}
__device__ __forceinline__ void cp_commit() {
    asm volatile("cp.async.commit_group;\n" ::: "memory");
}
template <int N>
__device__ __forceinline__ void cp_wait() {
    asm volatile("cp.async.wait_group %0;\n" :: "n"(N) : "memory");
}

__global__ __launch_bounds__(256)
void avid_cma_kernel(const float* __restrict__ video,
                     const float* __restrict__ audio,
                     const float4* __restrict__ m1,
                     const float4* __restrict__ m2,
                     const int* __restrict__ y,
                     const int* __restrict__ pos_idx,
                     const int* __restrict__ neg_idx,
                     float* __restrict__ out)
{
    extern __shared__ char ring[];            // D_ST * STAGE_B
    __shared__ int    sidx[NEG_PER_BLK];
    __shared__ float4 sv[32];
    __shared__ float4 sa[32];
    __shared__ float  sout[4][NEG_PER_BLK];   // O1,O3,O5,O7 staging

    const int b    = blockIdx.x;
    const int q    = blockIdx.y;
    const int tid  = threadIdx.x;
    const int lane = tid & 31;
    const int w    = tid >> 5;          // 8 warps
    const int c    = lane & 7;          // chunk within row (c, c+8, c+16, c+24)
    const int r    = lane >> 3;         // 8-lane group id in warp

    // --- preload this block's 256 negative indices ---
    sidx[tid] = __ldg(neg_idx + (size_t)b * NUM_NEG + (size_t)q * NEG_PER_BLK + tid);

    // --- normalize fresh embeddings ---
    if (w == 0) {
        float4 x = reinterpret_cast<const float4*>(video)[b * 32 + lane];
        float ss = warp_sum(dot4(x, x));
        float inv = 1.0f / fmaxf(sqrtf(ss), 1e-12f);
        sv[lane] = make_float4(x.x * inv, x.y * inv, x.z * inv, x.w * inv);
    } else if (w == 1) {
        float4 x = reinterpret_cast<const float4*>(audio)[b * 32 + lane];
        float ss = warp_sum(dot4(x, x));
        float inv = 1.0f / fmaxf(sqrtf(ss), 1e-12f);
        sa[lane] = make_float4(x.x * inv, x.y * inv, x.z * inv, x.w * inv);
    }
    __syncthreads();   // sidx + sv/sa visible to all warps

    const float4 v0 = sv[c], v1 = sv[c + 8], v2 = sv[c + 16], v3 = sv[c + 24];
    const float4 a0 = sa[c], a1 = sa[c + 8], a2 = sa[c + 16], a3 = sa[c + 24];

    // --- prologue: issue first D_ST-1 stages (warp-local groups) ---
#pragma unroll
    for (int s = 0; s < D_ST - 1; ++s) {
#pragma unroll
        for (int i = 0; i < 4; ++i) {
            const int t    = w * 4 + i;                 // row slot 0..31 (warp-owned)
            const int ni   = sidx[s * NEG_ST + (t >> 1)];
            const float4* src = ((t & 1) ? m2 : m1) + (size_t)ni * 32 + lane;
            uint32_t dst = (uint32_t)__cvta_generic_to_shared(
                ring + (size_t)s * STAGE_B + (size_t)t * 512 + lane * 16);
            cp_async16(dst, src);
        }
        cp_commit();
    }

    // --- pos + self dots (q==0 only), plain LDG while pipeline fills ---
    if (q == 0) {
        const int j  = w * 4 + r;
        const int pi = __ldg(pos_idx + (size_t)b * POS_K + j);
        const float4* p1 = m1 + (size_t)pi * 32 + c;
        const float4* p2 = m2 + (size_t)pi * 32 + c;
        float dvv = dot4(p1[0], v0) + dot4(p1[8], v1) + dot4(p1[16], v2) + dot4(p1[24], v3);
        float daa = dot4(p2[0], a0) + dot4(p2[8], a1) + dot4(p2[16], a2) + dot4(p2[24], a3);
        grp8_sum2(dvv, daa);
        if (c == 0) {
            out[O4 + (size_t)b * POS_K + j] = dvv * INV_TEMP;
            out[O6 + (size_t)b * POS_K + j] = daa * INV_TEMP;
        }
        if (w == 0 && r < 2) {
            const int yi = __ldg(y + b);
            const float4* p = (r == 0 ? m1 : m2) + (size_t)yi * 32 + c;
            float d;
            if (r == 0) d = dot4(p[0], a0) + dot4(p[8], a1) + dot4(p[16], a2) + dot4(p[24], a3);
            else        d = dot4(p[0], v0) + dot4(p[8], v1) + dot4(p[16], v2) + dot4(p[24], v3);
#pragma unroll
            for (int o = 4; o; o >>= 1) d += __shfl_xor_sync(0x0000ffffu, d, o);
            if (c == 0) {
                if (r == 0) out[O2 + b] = d * INV_TEMP;  // inst_a2v_pos
                else        out[O0 + b] = d * INV_TEMP;  // inst_v2a_pos
            }
        }
    }

    // --- main pipeline: per-warp, fully decoupled (no block barrier) ---
    // Warp w loads AND consumes rows w*4..w*4+3 of every stage, so only
    // warp-level sync is required.
    const int t = w * 4 + r;                    // this group's row slot (fixed)
    for (int s = 0; s < N_STAGE; ++s) {
        cp_wait<D_ST - 2>();                    // this warp's stage-s copies done
        __syncwarp();                           // cross-lane visibility in warp

        // issue stage s + D_ST - 1 first (slot (s-1)%D_ST is free for this warp)
        const int sn = s + D_ST - 1;
        if (sn < N_STAGE) {
#pragma unroll
            for (int i = 0; i < 4; ++i) {
                const int tt = w * 4 + i;
                const int ni = sidx[sn * NEG_ST + (tt >> 1)];
                const float4* src = ((tt & 1) ? m2 : m1) + (size_t)ni * 32 + lane;
                uint32_t dst = (uint32_t)__cvta_generic_to_shared(
                    ring + (size_t)(sn % D_ST) * STAGE_B + (size_t)tt * 512 + lane * 16);
                cp_async16(dst, src);
            }
        }
        cp_commit();                            // always commit (keeps group count)

        // compute: group handles row slot t of stage s
        const float4* buf = reinterpret_cast<const float4*>(
            ring + (size_t)(s % D_ST) * STAGE_B) + (size_t)t * 32;
        const float4 x0 = buf[c], x1 = buf[c + 8], x2 = buf[c + 16], x3 = buf[c + 24];
        float dv = dot4(x0, v0) + dot4(x1, v1) + dot4(x2, v2) + dot4(x3, v3);
        float da = dot4(x0, a0) + dot4(x1, a1) + dot4(x2, a2) + dot4(x3, a3);
        grp8_sum2(dv, da);
        if (c == 0) {
            const int j = s * NEG_ST + (t >> 1);
            if ((t & 1) == 0) {                 // m1 row: ·a -> O3, ·v -> O5
                sout[1][j] = da * INV_TEMP;
                sout[2][j] = dv * INV_TEMP;
            } else {                            // m2 row: ·v -> O1, ·a -> O7
                sout[0][j] = dv * INV_TEMP;
                sout[3][j] = da * INV_TEMP;
            }
        }
    }

    // --- coalesced output flush ---
    __syncthreads();
    const size_t o = (size_t)b * NUM_NEG + (size_t)q * NEG_PER_BLK + tid;
    out[O1 + o] = sout[0][tid];
    out[O3 + o] = sout[1][tid];
    out[O5 + o] = sout[2][tid];
    out[O7 + o] = sout[3][tid];
}

extern "C" void kernel_launch(void* const* d_in, const int* in_sizes, int n_in,
                              void* d_out, int out_size)
{
    const float* video = (const float*)d_in[0];
    const float* audio = (const float*)d_in[1];
    const float4* m1   = (const float4*)d_in[2];
    const float4* m2   = (const float4*)d_in[3];
    const int* y       = (const int*)d_in[4];
    const int* pos_idx = (const int*)d_in[5];
    const int* neg_idx = (const int*)d_in[6];
    float* out         = (float*)d_out;

    const int dyn_smem = D_ST * STAGE_B;   // 96 KB
    cudaFuncSetAttribute(avid_cma_kernel,
                         cudaFuncAttributeMaxDynamicSharedMemorySize, dyn_smem);

    dim3 grid(BS, NUM_NEG / NEG_PER_BLK);  // 512 x 4
    avid_cma_kernel<<<grid, 256, dyn_smem>>>(video, audio, m1, m2, y,
                                             pos_idx, neg_idx, out);
}

// round 5
// speedup vs baseline: 1.3879x; 1.0027x over previous
#include <cuda_runtime.h>
#include <cstdint>

#define BS      512
#define DIM     128
#define POS_K   32
#define NUM_NEG 1024
#define NEG_PER_BLK 256
#define INV_TEMP (1.0f / 0.07f)

#define D_ST    4                         // pipeline depth (stages in ring)
#define NEG_ST  16                        // negatives per stage
#define ROWS_ST (NEG_ST * 2)              // 32 rows (m1+m2) per stage
#define STAGE_B (ROWS_ST * 512)           // 16 KB per stage
#define N_STAGE (NEG_PER_BLK / NEG_ST)    // 16 stages per block

// Output layout (flattened tuple, float32):
#define O0 0          // inst_v2a_pos [512,1]
#define O1 512        // inst_v2a_neg [512,1024]
#define O2 524800     // inst_a2v_pos [512,1]
#define O3 525312     // inst_a2v_neg [512,1024]
#define O4 1049600    // pos_v2v_pos  [512,32]
#define O5 1065984    // pos_v2v_neg  [512,1024]
#define O6 1590272    // pos_a2a_pos  [512,32]
#define O7 1606656    // pos_a2a_neg  [512,1024]

__device__ __forceinline__ float warp_sum(float x) {
#pragma unroll
    for (int o = 16; o; o >>= 1) x += __shfl_xor_sync(0xffffffffu, x, o);
    return x;
}

__device__ __forceinline__ float dot4(float4 x, float4 y) {
    return x.x * y.x + x.y * y.y + x.z * y.z + x.w * y.w;
}

__device__ __forceinline__ void grp8_sum2(float& a, float& b) {
#pragma unroll
    for (int o = 4; o; o >>= 1) {
        a += __shfl_xor_sync(0xffffffffu, a, o);
        b += __shfl_xor_sync(0xffffffffu, b, o);
    }
}

__device__ __forceinline__ void cp_async16(uint32_t dst_smem, const void* src) {
    asm volatile("cp.async.cg.shared.global [%0], [%1], 16;\n"
                 :: "r"(dst_smem), "l"(src) : "memory");
}
__device__ __forceinline__ void cp_commit() {
    asm volatile("cp.async.commit_group;\n" ::: "memory");
}
template <int N>
__device__ __forceinline__ void cp_wait() {
    asm volatile("cp.async.wait_group %0;\n" :: "n"(N) : "memory");
}

__global__ __launch_bounds__(256, 3)
void avid_cma_kernel(const float* __restrict__ video,
                     const float* __restrict__ audio,
                     const float4* __restrict__ m1,
                     const float4* __restrict__ m2,
                     const int* __restrict__ y,
                     const int* __restrict__ pos_idx,
                     const int* __restrict__ neg_idx,
                     float* __restrict__ out)
{
    extern __shared__ char ring[];            // D_ST * STAGE_B = 64 KB
    __shared__ int    sidx[NEG_PER_BLK];
    __shared__ float4 sv[32];
    __shared__ float4 sa[32];
    __shared__ float  sout[4][NEG_PER_BLK];   // O1,O3,O5,O7 staging

    const int b    = blockIdx.x;
    const int q    = blockIdx.y;
    const int tid  = threadIdx.x;
    const int lane = tid & 31;
    const int w    = tid >> 5;          // 8 warps
    const int c    = lane & 7;          // chunk within row (c, c+8, c+16, c+24)
    const int r    = lane >> 3;         // 8-lane group id in warp

    // --- preload this block's 256 negative indices ---
    sidx[tid] = __ldg(neg_idx + (size_t)b * NUM_NEG + (size_t)q * NEG_PER_BLK + tid);

    // --- normalize fresh embeddings ---
    if (w == 0) {
        float4 x = reinterpret_cast<const float4*>(video)[b * 32 + lane];
        float ss = warp_sum(dot4(x, x));
        float inv = 1.0f / fmaxf(sqrtf(ss), 1e-12f);
        sv[lane] = make_float4(x.x * inv, x.y * inv, x.z * inv, x.w * inv);
    } else if (w == 1) {
        float4 x = reinterpret_cast<const float4*>(audio)[b * 32 + lane];
        float ss = warp_sum(dot4(x, x));
        float inv = 1.0f / fmaxf(sqrtf(ss), 1e-12f);
        sa[lane] = make_float4(x.x * inv, x.y * inv, x.z * inv, x.w * inv);
    }
    __syncthreads();   // sidx + sv/sa visible to all warps

    const float4 v0 = sv[c], v1 = sv[c + 8], v2 = sv[c + 16], v3 = sv[c + 24];
    const float4 a0 = sa[c], a1 = sa[c + 8], a2 = sa[c + 16], a3 = sa[c + 24];

    // --- prologue: issue first D_ST-1 stages (warp-local groups) ---
#pragma unroll
    for (int s = 0; s < D_ST - 1; ++s) {
#pragma unroll
        for (int i = 0; i < 4; ++i) {
            const int t    = w * 4 + i;                 // row slot 0..31 (warp-owned)
            const int ni   = sidx[s * NEG_ST + (t >> 1)];
            const float4* src = ((t & 1) ? m2 : m1) + (size_t)ni * 32 + lane;
            uint32_t dst = (uint32_t)__cvta_generic_to_shared(
                ring + (size_t)s * STAGE_B + (size_t)t * 512 + lane * 16);
            cp_async16(dst, src);
        }
        cp_commit();
    }

    // --- pos + self dots (q==0 only), plain LDG while pipeline fills ---
    if (q == 0) {
        const int j  = w * 4 + r;
        const int pi = __ldg(pos_idx + (size_t)b * POS_K + j);
        const float4* p1 = m1 + (size_t)pi * 32 + c;
        const float4* p2 = m2 + (size_t)pi * 32 + c;
        float dvv = dot4(p1[0], v0) + dot4(p1[8], v1) + dot4(p1[16], v2) + dot4(p1[24], v3);
        float daa = dot4(p2[0], a0) + dot4(p2[8], a1) + dot4(p2[16], a2) + dot4(p2[24], a3);
        grp8_sum2(dvv, daa);
        if (c == 0) {
            out[O4 + (size_t)b * POS_K + j] = dvv * INV_TEMP;
            out[O6 + (size_t)b * POS_K + j] = daa * INV_TEMP;
        }
        if (w == 0 && r < 2) {
            const int yi = __ldg(y + b);
            const float4* p = (r == 0 ? m1 : m2) + (size_t)yi * 32 + c;
            float d;
            if (r == 0) d = dot4(p[0], a0) + dot4(p[8], a1) + dot4(p[16], a2) + dot4(p[24], a3);
            else        d = dot4(p[0], v0) + dot4(p[8], v1) + dot4(p[16], v2) + dot4(p[24], v3);
#pragma unroll
            for (int o = 4; o; o >>= 1) d += __shfl_xor_sync(0x0000ffffu, d, o);
            if (c == 0) {
                if (r == 0) out[O2 + b] = d * INV_TEMP;  // inst_a2v_pos
                else        out[O0 + b] = d * INV_TEMP;  // inst_v2a_pos
            }
        }
    }

    // --- main pipeline: per-warp, fully decoupled (no block barrier) ---
    // Warp w loads AND consumes rows w*4..w*4+3 of every stage, so only
    // warp-level sync is required.
    const int t = w * 4 + r;                    // this group's row slot (fixed)
    for (int s = 0; s < N_STAGE; ++s) {
        cp_wait<D_ST - 2>();                    // this warp's stage-s copies done
        __syncwarp();                           // cross-lane visibility in warp

        // issue stage s + D_ST - 1 first (that ring slot is free for this warp)
        const int sn = s + D_ST - 1;
        if (sn < N_STAGE) {
#pragma unroll
            for (int i = 0; i < 4; ++i) {
                const int tt = w * 4 + i;
                const int ni = sidx[sn * NEG_ST + (tt >> 1)];
                const float4* src = ((tt & 1) ? m2 : m1) + (size_t)ni * 32 + lane;
                uint32_t dst = (uint32_t)__cvta_generic_to_shared(
                    ring + (size_t)(sn % D_ST) * STAGE_B + (size_t)tt * 512 + lane * 16);
                cp_async16(dst, src);
            }
        }
        cp_commit();                            // always commit (keeps group count)

        // compute: group handles row slot t of stage s
        const float4* buf = reinterpret_cast<const float4*>(
            ring + (size_t)(s % D_ST) * STAGE_B) + (size_t)t * 32;
        const float4 x0 = buf[c], x1 = buf[c + 8], x2 = buf[c + 16], x3 = buf[c + 24];
        float dv = dot4(x0, v0) + dot4(x1, v1) + dot4(x2, v2) + dot4(x3, v3);
        float da = dot4(x0, a0) + dot4(x1, a1) + dot4(x2, a2) + dot4(x3, a3);
        grp8_sum2(dv, da);
        if (c == 0) {
            const int j = s * NEG_ST + (t >> 1);
            if ((t & 1) == 0) {                 // m1 row: ·a -> O3, ·v -> O5
                sout[1][j] = da * INV_TEMP;
                sout[2][j] = dv * INV_TEMP;
            } else {                            // m2 row: ·v -> O1, ·a -> O7
                sout[0][j] = dv * INV_TEMP;
                sout[3][j] = da * INV_TEMP;
            }
        }
    }

    // --- coalesced output flush ---
    __syncthreads();
    const size_t o = (size_t)b * NUM_NEG + (size_t)q * NEG_PER_BLK + tid;
    out[O1 + o] = sout[0][tid];
    out[O3 + o] = sout[1][tid];
    out[O5 + o] = sout[2][tid];
    out[O7 + o] = sout[3][tid];
}

extern "C" void kernel_launch(void* const* d_in, const int* in_sizes, int n_in,
                              void* d_out, int out_size)
{
    const float* video = (const float*)d_in[0];
    const float* audio = (const float*)d_in[1];
    const float4* m1   = (const float4*)d_in[2];
    const float4* m2   = (const float4*)d_in[3];
    const int* y       = (const int*)d_in[4];
    const int* pos_idx = (const int*)d_in[5];
    const int* neg_idx = (const int*)d_in[6];
    float* out         = (float*)d_out;

    const int dyn_smem = D_ST * STAGE_B;   // 64 KB
    cudaFuncSetAttribute(avid_cma_kernel,
                         cudaFuncAttributeMaxDynamicSharedMemorySize, dyn_smem);

    dim3 grid(BS, NUM_NEG / NEG_PER_BLK);  // 512 x 4
    avid_cma_kernel<<<grid, 256, dyn_smem>>>(video, audio, m1, m2, y,
                                             pos_idx, neg_idx, out);
}